// round 1
// baseline (speedup 1.0000x reference)
#include <cuda_runtime.h>
#include <math.h>

// ---------------- problem constants ----------------
#define BB     4
#define CLID   128
#define HH     256
#define WW     256
#define HWSZ   65536
#define CCAM   256
#define NTOK   8192
#define HDIM   128
#define NHEADS 4
#define DHEAD  32
#define MTOT   (BB*NTOK)          // 32768 tokens total
#define SCALE  0.17677669529663687f  // 1/sqrt(32)

// ---------------- GEMM tiling ----------------
#define BM 64
#define BN 128
#define BK 16
// 256 threads: tx = tid&15 -> 8 cols each, ty = tid>>4 -> 4 rows each

// ---------------- scratch (device globals; no runtime alloc) ----------------
__device__ float  g_k[MTOT*HDIM];          // 16.8 MB
__device__ float  g_v[MTOT*HDIM];          // 16.8 MB
__device__ float  g_logit[BB*NHEADS*NTOK]; // 512 KB
__device__ float2 g_red[BB*NHEADS];        // (max, 1/sumexp)

// ============================================================
// Kernel A: out = lidar + alpha*out_bias[c]   (dense, float4)
// ============================================================
__global__ void k_init(const float4* __restrict__ lidar,
                       const float*  __restrict__ alpha_p,
                       const float*  __restrict__ out_bias,
                       float4* __restrict__ out)
{
    int i = blockIdx.x * blockDim.x + threadIdx.x;   // float4 index, 0..8388607
    float alpha = *alpha_p;
    int c = (i >> 14) & 127;                         // (i*4/65536) % 128
    float bv = alpha * out_bias[c];
    float4 v = lidar[i];
    v.x += bv; v.y += bv; v.z += bv; v.w += bv;
    out[i] = v;
}

// ============================================================
// Kernel B: K = tok @ k_w^T, V = tok @ v_w^T  (M=32768,N=128,K=256)
// blockIdx.y: 0 -> K, 1 -> V
// ============================================================
__global__ void __launch_bounds__(256)
k_kv(const float* __restrict__ tok,
     const float* __restrict__ k_w,
     const float* __restrict__ v_w)
{
    __shared__ float sA[BK][BM + 4];   // padded (stride 68 -> 16B aligned rows)
    __shared__ float sB[BK][BN + 4];   // padded (stride 132 -> 16B aligned rows)

    const int m0  = blockIdx.x * BM;
    const float* w    = blockIdx.y ? v_w : k_w;
    float*       outp = blockIdx.y ? g_v : g_k;
    const int tid = threadIdx.x;
    const int tx = tid & 15, ty = tid >> 4;

    float acc[4][8];
#pragma unroll
    for (int i = 0; i < 4; i++)
#pragma unroll
        for (int j = 0; j < 8; j++) acc[i][j] = 0.f;

    for (int k0 = 0; k0 < CCAM; k0 += BK) {
        {   // stage A tile (tok), transposed
            int row = tid >> 2, cq = tid & 3;
            float4 v = *(const float4*)(tok + (size_t)(m0 + row) * CCAM + k0 + cq * 4);
            sA[cq*4+0][row] = v.x; sA[cq*4+1][row] = v.y;
            sA[cq*4+2][row] = v.z; sA[cq*4+3][row] = v.w;
        }
#pragma unroll
        for (int l = 0; l < 2; l++) {   // stage W tile, transposed
            int n = (tid >> 2) + l * 64, cq = tid & 3;
            float4 v = *(const float4*)(w + (size_t)n * CCAM + k0 + cq * 4);
            sB[cq*4+0][n] = v.x; sB[cq*4+1][n] = v.y;
            sB[cq*4+2][n] = v.z; sB[cq*4+3][n] = v.w;
        }
        __syncthreads();
#pragma unroll
        for (int kk = 0; kk < BK; kk++) {
            float4 a  = *(const float4*)&sA[kk][ty * 4];
            float4 b0 = *(const float4*)&sB[kk][tx * 8];
            float4 b1 = *(const float4*)&sB[kk][tx * 8 + 4];
            float av[4] = {a.x, a.y, a.z, a.w};
            float bv[8] = {b0.x, b0.y, b0.z, b0.w, b1.x, b1.y, b1.z, b1.w};
#pragma unroll
            for (int i = 0; i < 4; i++)
#pragma unroll
                for (int j = 0; j < 8; j++)
                    acc[i][j] += av[i] * bv[j];
        }
        __syncthreads();
    }
#pragma unroll
    for (int i = 0; i < 4; i++) {
        size_t r = (size_t)(m0 + ty * 4 + i) * HDIM;
        float4 o0 = {acc[i][0], acc[i][1], acc[i][2], acc[i][3]};
        float4 o1 = {acc[i][4], acc[i][5], acc[i][6], acc[i][7]};
        *(float4*)(outp + r + tx * 8)     = o0;
        *(float4*)(outp + r + tx * 8 + 4) = o1;
    }
}

// ============================================================
// Kernel C: gather lidar at token pixels, q = q_w@x + q_bias (regs only),
// logit[b,h,t] = SCALE * <q_head, k_head>   (M=32768,N=128,K=128)
// ============================================================
__global__ void __launch_bounds__(256)
k_qlogit(const float* __restrict__ lidar,
         const int*   __restrict__ ind,
         const float* __restrict__ q_w,
         const float* __restrict__ q_bias)
{
    __shared__ float sA[BK][BM + 4];
    __shared__ float sB[BK][BN + 4];
    __shared__ int   spix[BM];

    const int m0    = blockIdx.x * BM;
    const int batch = m0 >> 13;                 // 8192 tokens per batch, BM|8192
    const int tid   = threadIdx.x;

    if (tid < BM) {
        int t  = m0 + tid;
        int ii = ind[t * 2 + 0], jj = ind[t * 2 + 1];
        ii = min(max(ii, 0), HH - 1);
        jj = min(max(jj, 0), WW - 1);
        spix[tid] = ii * WW + jj;
    }
    __syncthreads();

    const int tx = tid & 15, ty = tid >> 4;
    float acc[4][8];
#pragma unroll
    for (int i = 0; i < 4; i++)
#pragma unroll
        for (int j = 0; j < 8; j++) acc[i][j] = 0.f;

    const float* lb = lidar + (size_t)batch * CLID * HWSZ;

    for (int k0 = 0; k0 < CLID; k0 += BK) {
#pragma unroll
        for (int l = 0; l < 4; l++) {           // scattered gather: sA[c][t]
            int idx = tid + l * 256;
            int c = idx >> 6, i = idx & 63;
            sA[c][i] = lb[(size_t)(k0 + c) * HWSZ + spix[i]];
        }
#pragma unroll
        for (int l = 0; l < 2; l++) {
            int n = (tid >> 2) + l * 64, cq = tid & 3;
            float4 v = *(const float4*)(q_w + (size_t)n * CLID + k0 + cq * 4);
            sB[cq*4+0][n] = v.x; sB[cq*4+1][n] = v.y;
            sB[cq*4+2][n] = v.z; sB[cq*4+3][n] = v.w;
        }
        __syncthreads();
#pragma unroll
        for (int kk = 0; kk < BK; kk++) {
            float4 a  = *(const float4*)&sA[kk][ty * 4];
            float4 b0 = *(const float4*)&sB[kk][tx * 8];
            float4 b1 = *(const float4*)&sB[kk][tx * 8 + 4];
            float av[4] = {a.x, a.y, a.z, a.w};
            float bv[8] = {b0.x, b0.y, b0.z, b0.w, b1.x, b1.y, b1.z, b1.w};
#pragma unroll
            for (int i = 0; i < 4; i++)
#pragma unroll
                for (int j = 0; j < 8; j++)
                    acc[i][j] += av[i] * bv[j];
        }
        __syncthreads();
    }

    // add q_bias, then per-token per-head dot with K (8 cols/thread live in one head)
    float4 qb0 = *(const float4*)(q_bias + tx * 8);
    float4 qb1 = *(const float4*)(q_bias + tx * 8 + 4);
    const int h = tx >> 2;
#pragma unroll
    for (int i = 0; i < 4; i++) {
        int r = m0 + ty * 4 + i;
        const float* kp = g_k + (size_t)r * HDIM + tx * 8;
        float4 k0v = *(const float4*)(kp);
        float4 k1v = *(const float4*)(kp + 4);
        float p = (acc[i][0] + qb0.x) * k0v.x + (acc[i][1] + qb0.y) * k0v.y
                + (acc[i][2] + qb0.z) * k0v.z + (acc[i][3] + qb0.w) * k0v.w
                + (acc[i][4] + qb1.x) * k1v.x + (acc[i][5] + qb1.y) * k1v.y
                + (acc[i][6] + qb1.z) * k1v.z + (acc[i][7] + qb1.w) * k1v.w;
        // reduce over the 4 tx-lanes that share this head
        p += __shfl_xor_sync(0xffffffffu, p, 1);
        p += __shfl_xor_sync(0xffffffffu, p, 2);
        if ((tx & 3) == 0)
            g_logit[(batch * NHEADS + h) * NTOK + (r - batch * NTOK)] = p * SCALE;
    }
}

// ============================================================
// Kernel D: per (b,head) max + sumexp over 8192 logits
// ============================================================
__global__ void k_softred()
{
    const int bh = blockIdx.x;
    const float* lp = g_logit + bh * NTOK;
    __shared__ float red[256];
    int tid = threadIdx.x;

    float m = -1e30f;
    for (int i = tid; i < NTOK; i += 256) m = fmaxf(m, lp[i]);
    red[tid] = m; __syncthreads();
    for (int s = 128; s > 0; s >>= 1) {
        if (tid < s) red[tid] = fmaxf(red[tid], red[tid + s]);
        __syncthreads();
    }
    float mx = red[0]; __syncthreads();

    float sum = 0.f;
    for (int i = tid; i < NTOK; i += 256) sum += expf(lp[i] - mx);
    red[tid] = sum; __syncthreads();
    for (int s = 128; s > 0; s >>= 1) {
        if (tid < s) red[tid] += red[tid + s];
        __syncthreads();
    }
    if (tid == 0) g_red[bh] = make_float2(mx, 1.0f / red[0]);
}

// ============================================================
// Kernel E: attn = exp(logit-mx)/sum * gw * alpha; fused = attn*V;
// y = out_w @ fused; atomicAdd-scatter into out  (M=32768,N=128,K=128)
// ============================================================
__global__ void __launch_bounds__(256)
k_out(const int*   __restrict__ ind,
      const float* __restrict__ gw,
      const float* __restrict__ alpha_p,
      const float* __restrict__ out_w,
      float* __restrict__ out)
{
    __shared__ float sA[BK][BM + 4];
    __shared__ float sB[BK][BN + 4];
    __shared__ int   spix[BM];
    __shared__ float saw[BM][NHEADS];

    const int m0    = blockIdx.x * BM;
    const int batch = m0 >> 13;
    const int tid   = threadIdx.x;

    if (tid < BM) {
        int t  = m0 + tid;
        int ii = ind[t * 2 + 0], jj = ind[t * 2 + 1];
        ii = min(max(ii, 0), HH - 1);
        jj = min(max(jj, 0), WW - 1);
        spix[tid] = ii * WW + jj;
    }
    {   // attention weights: 64 tokens x 4 heads
        int t = tid & 63, h = tid >> 6;
        int tloc = (m0 & (NTOK - 1)) + t;
        float  lt = g_logit[(batch * NHEADS + h) * NTOK + tloc];
        float2 r  = g_red[batch * NHEADS + h];
        saw[t][h] = expf(lt - r.x) * r.y * gw[batch * NTOK + tloc] * (*alpha_p);
    }
    __syncthreads();

    const int tx = tid & 15, ty = tid >> 4;
    float acc[4][8];
#pragma unroll
    for (int i = 0; i < 4; i++)
#pragma unroll
        for (int j = 0; j < 8; j++) acc[i][j] = 0.f;

    for (int k0 = 0; k0 < HDIM; k0 += BK) {
        const int h = k0 >> 5;   // each 16-chunk lies within one head
        {
            int row = tid >> 2, cq = tid & 3;
            float4 v = *(const float4*)(g_v + (size_t)(m0 + row) * HDIM + k0 + cq * 4);
            float wgt = saw[row][h];
            sA[cq*4+0][row] = v.x * wgt; sA[cq*4+1][row] = v.y * wgt;
            sA[cq*4+2][row] = v.z * wgt; sA[cq*4+3][row] = v.w * wgt;
        }
#pragma unroll
        for (int l = 0; l < 2; l++) {
            int n = (tid >> 2) + l * 64, cq = tid & 3;
            float4 v = *(const float4*)(out_w + (size_t)n * HDIM + k0 + cq * 4);
            sB[cq*4+0][n] = v.x; sB[cq*4+1][n] = v.y;
            sB[cq*4+2][n] = v.z; sB[cq*4+3][n] = v.w;
        }
        __syncthreads();
#pragma unroll
        for (int kk = 0; kk < BK; kk++) {
            float4 a  = *(const float4*)&sA[kk][ty * 4];
            float4 b0 = *(const float4*)&sB[kk][tx * 8];
            float4 b1 = *(const float4*)&sB[kk][tx * 8 + 4];
            float av[4] = {a.x, a.y, a.z, a.w};
            float bv[8] = {b0.x, b0.y, b0.z, b0.w, b1.x, b1.y, b1.z, b1.w};
#pragma unroll
            for (int i = 0; i < 4; i++)
#pragma unroll
                for (int j = 0; j < 8; j++)
                    acc[i][j] += av[i] * bv[j];
        }
        __syncthreads();
    }

    float* ob = out + (size_t)batch * CLID * HWSZ;
#pragma unroll
    for (int i = 0; i < 4; i++) {
        int t = ty * 4 + i;
        int pix = spix[t];
#pragma unroll
        for (int j = 0; j < 8; j++)
            atomicAdd(ob + (size_t)(tx * 8 + j) * HWSZ + pix, acc[i][j]);
    }
}

// ============================================================
extern "C" void kernel_launch(void* const* d_in, const int* in_sizes, int n_in,
                              void* d_out, int out_size)
{
    const float* lidar = (const float*)d_in[0];
    const float* tok   = (const float*)d_in[1];
    const int*   ind   = (const int*)  d_in[2];
    const float* gw    = (const float*)d_in[3];
    const float* alpha = (const float*)d_in[4];
    const float* q_w   = (const float*)d_in[5];
    const float* q_b   = (const float*)d_in[6];
    const float* k_w   = (const float*)d_in[7];
    const float* v_w   = (const float*)d_in[8];
    const float* o_w   = (const float*)d_in[9];
    const float* o_b   = (const float*)d_in[10];
    float* out = (float*)d_out;

    // dense init: out = lidar + alpha*out_bias
    k_init<<<(BB * CLID * HWSZ) / 4 / 256, 256>>>((const float4*)lidar, alpha, o_b, (float4*)out);
    // K,V projections
    dim3 gb(MTOT / BM, 2);
    k_kv<<<gb, 256>>>(tok, k_w, v_w);
    // gathered Q + diagonal logits
    k_qlogit<<<MTOT / BM, 256>>>(lidar, ind, q_w, q_b);
    // softmax reductions
    k_softred<<<BB * NHEADS, 256>>>();
    // weighted V -> out_w projection -> scatter-add
    k_out<<<MTOT / BM, 256>>>(ind, gw, alpha, o_w, out);
}

// round 2
// speedup vs baseline: 1.6816x; 1.6816x over previous
#include <cuda_runtime.h>
#include <cuda_bf16.h>
#include <math.h>
#include <stdint.h>

// ---------------- problem constants ----------------
#define BB     4
#define CLID   128
#define HH     256
#define WW     256
#define HWSZ   65536
#define CCAM   256
#define NTOK   8192
#define HDIM   128
#define NHEADS 4
#define MTOT   (BB*NTOK)             // 32768 tokens
#define SCALE  0.17677669529663687f  // 1/sqrt(32)

// ---------------- GEMM tiling ----------------
#define BM 128
#define BN 128
#define BK 32
#define SAW 20    // smem row stride in 32-bit words (BK/2 + 4) -> conflict-free

// ---------------- scratch (device globals) ----------------
// bf16 matrices stored as packed uint32 (2 halves / word), row stride 64 words
__device__ uint32_t g_k[MTOT*64];           // K  [32768][128] bf16
__device__ uint32_t g_v[MTOT*64];           // V  [32768][128] bf16
__device__ uint32_t g_q[MTOT*64];           // Q  [32768][128] bf16
__device__ float    g_logit[BB*NHEADS*NTOK];
__device__ float2   g_red[BB*NHEADS];       // (max, 1/sumexp)

// ---------------- helpers ----------------
__device__ __forceinline__ uint32_t f2b(float x, float y) {
    __nv_bfloat162 h = __floats2bfloat162_rn(x, y);
    return *reinterpret_cast<uint32_t*>(&h);
}
__device__ __forceinline__ float2 b2f(uint32_t u) {
    __nv_bfloat162 h = *reinterpret_cast<__nv_bfloat162*>(&u);
    return __bfloat1622float2(h);
}

#define MMA(d, a0,a1,a2,a3, b0,b1)                                              \
    asm volatile("mma.sync.aligned.m16n8k16.row.col.f32.bf16.bf16.f32 "         \
                 "{%0,%1,%2,%3},{%4,%5,%6,%7},{%8,%9},{%0,%1,%2,%3};"           \
                 : "+f"(d[0]), "+f"(d[1]), "+f"(d[2]), "+f"(d[3])               \
                 : "r"(a0), "r"(a1), "r"(a2), "r"(a3), "r"(b0), "r"(b1))

// fragment math shared by all GEMM kernels:
//   256 threads = 8 warps, warp grid 4(m) x 2(n); warp tile 32m x 64n
//   m-frags: 2 x m16, n-frags: 8 x n8; k-steps: BK/16 = 2

// ============================================================
// Kernel A: out = lidar + alpha*out_bias[c]   (dense, float4)
// ============================================================
__global__ void k_init(const float4* __restrict__ lidar,
                       const float*  __restrict__ alpha_p,
                       const float*  __restrict__ out_bias,
                       float4* __restrict__ out)
{
    int i = blockIdx.x * blockDim.x + threadIdx.x;
    float alpha = *alpha_p;
    int c = (i >> 14) & 127;
    float bv = alpha * out_bias[c];
    float4 v = lidar[i];
    v.x += bv; v.y += bv; v.z += bv; v.w += bv;
    out[i] = v;
}

// ============================================================
// Kernel B: K = tok @ k_w^T, V = tok @ v_w^T  (M=32768,N=128,K=256) bf16 MMA
// blockIdx.y: 0 -> K, 1 -> V
// ============================================================
__global__ void __launch_bounds__(256)
k_kv(const float* __restrict__ tok,
     const float* __restrict__ k_w,
     const float* __restrict__ v_w)
{
    __shared__ uint32_t sA[BM * SAW];
    __shared__ uint32_t sB[BN * SAW];

    const int m0 = blockIdx.x * BM;
    const float* w = blockIdx.y ? v_w : k_w;
    uint32_t* outp = blockIdx.y ? g_v : g_k;

    const int tid  = threadIdx.x;
    const int lane = tid & 31, wid = tid >> 5;
    const int wm = (wid & 3) * 32, wn = (wid >> 2) * 64;
    const int g = lane >> 2, t = lane & 3;

    float acc[2][8][4];
#pragma unroll
    for (int i = 0; i < 2; i++)
#pragma unroll
        for (int j = 0; j < 8; j++)
#pragma unroll
            for (int q = 0; q < 4; q++) acc[i][j][q] = 0.f;

    for (int k0 = 0; k0 < CCAM; k0 += BK) {
#pragma unroll
        for (int i = 0; i < 4; i++) {           // stage A (tok) -> bf16
            int f = tid + i * 256, row = f >> 3, c = f & 7;
            float4 v = *(const float4*)(tok + (size_t)(m0 + row) * CCAM + k0 + c * 4);
            sA[row * SAW + c * 2]     = f2b(v.x, v.y);
            sA[row * SAW + c * 2 + 1] = f2b(v.z, v.w);
        }
#pragma unroll
        for (int i = 0; i < 4; i++) {           // stage B (weights) -> bf16
            int f = tid + i * 256, row = f >> 3, c = f & 7;
            float4 v = *(const float4*)(w + (size_t)row * CCAM + k0 + c * 4);
            sB[row * SAW + c * 2]     = f2b(v.x, v.y);
            sB[row * SAW + c * 2 + 1] = f2b(v.z, v.w);
        }
        __syncthreads();
#pragma unroll
        for (int kk = 0; kk < 2; kk++) {
            uint32_t br[8][2];
#pragma unroll
            for (int fn = 0; fn < 8; fn++) {
                int n = wn + fn * 8 + g;
                br[fn][0] = sB[n * SAW + kk * 8 + t];
                br[fn][1] = sB[n * SAW + kk * 8 + t + 4];
            }
#pragma unroll
            for (int fm = 0; fm < 2; fm++) {
                int m = wm + fm * 16 + g;
                uint32_t a0 = sA[m * SAW + kk * 8 + t];
                uint32_t a1 = sA[(m + 8) * SAW + kk * 8 + t];
                uint32_t a2 = sA[m * SAW + kk * 8 + t + 4];
                uint32_t a3 = sA[(m + 8) * SAW + kk * 8 + t + 4];
#pragma unroll
                for (int fn = 0; fn < 8; fn++)
                    MMA(acc[fm][fn], a0, a1, a2, a3, br[fn][0], br[fn][1]);
            }
        }
        __syncthreads();
    }

#pragma unroll
    for (int fm = 0; fm < 2; fm++)
#pragma unroll
        for (int fn = 0; fn < 8; fn++) {
            int m = m0 + wm + fm * 16 + g;
            int wcol = wn / 2 + fn * 4 + t;     // word column (2 halves)
            outp[(size_t)m * 64 + wcol]       = f2b(acc[fm][fn][0], acc[fm][fn][1]);
            outp[(size_t)(m + 8) * 64 + wcol] = f2b(acc[fm][fn][2], acc[fm][fn][3]);
        }
}

// ============================================================
// Kernel C: gather lidar at token pixels -> Q = q_w@x + q_bias (bf16 MMA)
// ============================================================
__global__ void __launch_bounds__(256)
k_qgemm(const float* __restrict__ lidar,
        const int*   __restrict__ ind,
        const float* __restrict__ q_w,
        const float* __restrict__ q_bias)
{
    __shared__ uint32_t sA[BM * SAW];
    __shared__ uint32_t sB[BN * SAW];
    __shared__ int spix[BM];

    const int m0    = blockIdx.x * BM;
    const int batch = m0 >> 13;
    const int tid   = threadIdx.x;

    if (tid < BM) {
        int tk = m0 + tid;
        int ii = ind[tk * 2 + 0], jj = ind[tk * 2 + 1];
        ii = min(max(ii, 0), HH - 1);
        jj = min(max(jj, 0), WW - 1);
        spix[tid] = ii * WW + jj;
    }
    __syncthreads();

    const int lane = tid & 31, wid = tid >> 5;
    const int wm = (wid & 3) * 32, wn = (wid >> 2) * 64;
    const int g = lane >> 2, t = lane & 3;

    float acc[2][8][4];
#pragma unroll
    for (int i = 0; i < 2; i++)
#pragma unroll
        for (int j = 0; j < 8; j++)
#pragma unroll
            for (int q = 0; q < 4; q++) acc[i][j][q] = 0.f;

    const float* lb = lidar + (size_t)batch * CLID * HWSZ;

    for (int k0 = 0; k0 < CLID; k0 += BK) {
#pragma unroll
        for (int i = 0; i < 8; i++) {           // gather stage: 128 rows x 16 word-cols
            int f = tid + i * 256, row = f >> 4, p = f & 15;
            const float* lp = lb + (size_t)(k0 + 2 * p) * HWSZ + spix[row];
            sA[row * SAW + p] = f2b(lp[0], lp[HWSZ]);
        }
#pragma unroll
        for (int i = 0; i < 4; i++) {           // stage q_w
            int f = tid + i * 256, row = f >> 3, c = f & 7;
            float4 v = *(const float4*)(q_w + (size_t)row * CLID + k0 + c * 4);
            sB[row * SAW + c * 2]     = f2b(v.x, v.y);
            sB[row * SAW + c * 2 + 1] = f2b(v.z, v.w);
        }
        __syncthreads();
#pragma unroll
        for (int kk = 0; kk < 2; kk++) {
            uint32_t br[8][2];
#pragma unroll
            for (int fn = 0; fn < 8; fn++) {
                int n = wn + fn * 8 + g;
                br[fn][0] = sB[n * SAW + kk * 8 + t];
                br[fn][1] = sB[n * SAW + kk * 8 + t + 4];
            }
#pragma unroll
            for (int fm = 0; fm < 2; fm++) {
                int m = wm + fm * 16 + g;
                uint32_t a0 = sA[m * SAW + kk * 8 + t];
                uint32_t a1 = sA[(m + 8) * SAW + kk * 8 + t];
                uint32_t a2 = sA[m * SAW + kk * 8 + t + 4];
                uint32_t a3 = sA[(m + 8) * SAW + kk * 8 + t + 4];
#pragma unroll
                for (int fn = 0; fn < 8; fn++)
                    MMA(acc[fm][fn], a0, a1, a2, a3, br[fn][0], br[fn][1]);
            }
        }
        __syncthreads();
    }

#pragma unroll
    for (int fm = 0; fm < 2; fm++)
#pragma unroll
        for (int fn = 0; fn < 8; fn++) {
            int n0 = wn + fn * 8 + 2 * t;
            float2 qb = *(const float2*)(q_bias + n0);
            int m = m0 + wm + fm * 16 + g;
            int wcol = wn / 2 + fn * 4 + t;
            g_q[(size_t)m * 64 + wcol]       = f2b(acc[fm][fn][0] + qb.x, acc[fm][fn][1] + qb.y);
            g_q[(size_t)(m + 8) * 64 + wcol] = f2b(acc[fm][fn][2] + qb.x, acc[fm][fn][3] + qb.y);
        }
}

// ============================================================
// Kernel D: logits = SCALE*<q_h,k_h>, then per-(b,h) max + sumexp
// ============================================================
__global__ void __launch_bounds__(256)
k_logit_red()
{
    const int bh = blockIdx.x;
    const int b = bh >> 2, h = bh & 3;
    const int tid = threadIdx.x;
    const uint32_t* qb = g_q + (size_t)b * NTOK * 64 + h * 16;
    const uint32_t* kb = g_k + (size_t)b * NTOK * 64 + h * 16;
    float* lp = g_logit + (size_t)bh * NTOK;
    __shared__ float red[256];

    float mx = -1e30f;
    for (int tk = tid; tk < NTOK; tk += 256) {
        const uint32_t* q = qb + (size_t)tk * 64;
        const uint32_t* k = kb + (size_t)tk * 64;
        float s = 0.f;
#pragma unroll
        for (int w = 0; w < 16; w += 4) {
            uint4 qv = *(const uint4*)(q + w);
            uint4 kv = *(const uint4*)(k + w);
            float2 a, bx;
            a = b2f(qv.x); bx = b2f(kv.x); s += a.x * bx.x + a.y * bx.y;
            a = b2f(qv.y); bx = b2f(kv.y); s += a.x * bx.x + a.y * bx.y;
            a = b2f(qv.z); bx = b2f(kv.z); s += a.x * bx.x + a.y * bx.y;
            a = b2f(qv.w); bx = b2f(kv.w); s += a.x * bx.x + a.y * bx.y;
        }
        s *= SCALE;
        lp[tk] = s;
        mx = fmaxf(mx, s);
    }
    red[tid] = mx; __syncthreads();
    for (int s = 128; s > 0; s >>= 1) {
        if (tid < s) red[tid] = fmaxf(red[tid], red[tid + s]);
        __syncthreads();
    }
    mx = red[0]; __syncthreads();

    float sum = 0.f;
    for (int tk = tid; tk < NTOK; tk += 256) sum += expf(lp[tk] - mx);
    red[tid] = sum; __syncthreads();
    for (int s = 128; s > 0; s >>= 1) {
        if (tid < s) red[tid] += red[tid + s];
        __syncthreads();
    }
    if (tid == 0) g_red[bh] = make_float2(mx, 1.0f / red[0]);
}

// ============================================================
// Kernel E: fused = attn*V; y = out_w @ fused (bf16 MMA); scatter-add
// ============================================================
__global__ void __launch_bounds__(256)
k_out(const int*   __restrict__ ind,
      const float* __restrict__ gw,
      const float* __restrict__ alpha_p,
      const float* __restrict__ out_w,
      float* __restrict__ out)
{
    __shared__ uint32_t sA[BM * SAW];
    __shared__ uint32_t sB[BN * SAW];
    __shared__ int   spix[BM];
    __shared__ float saw[BM * NHEADS];

    const int m0    = blockIdx.x * BM;
    const int batch = m0 >> 13;
    const int tid   = threadIdx.x;

    if (tid < BM) {
        int tk = m0 + tid;
        int ii = ind[tk * 2 + 0], jj = ind[tk * 2 + 1];
        ii = min(max(ii, 0), HH - 1);
        jj = min(max(jj, 0), WW - 1);
        spix[tid] = ii * WW + jj;
    }
    {
        float alpha = *alpha_p;
#pragma unroll
        for (int j = 0; j < 2; j++) {
            int idx = tid + j * 256;            // 512 = 128 tokens x 4 heads
            int tl = idx & 127, h = idx >> 7;
            int tloc = (m0 & (NTOK - 1)) + tl;
            float  lt = g_logit[(size_t)(batch * NHEADS + h) * NTOK + tloc];
            float2 r  = g_red[batch * NHEADS + h];
            saw[tl * NHEADS + h] = expf(lt - r.x) * r.y * gw[(size_t)batch * NTOK + tloc] * alpha;
        }
    }
    __syncthreads();

    const int lane = tid & 31, wid = tid >> 5;
    const int wm = (wid & 3) * 32, wn = (wid >> 2) * 64;
    const int g = lane >> 2, t = lane & 3;

    float acc[2][8][4];
#pragma unroll
    for (int i = 0; i < 2; i++)
#pragma unroll
        for (int j = 0; j < 8; j++)
#pragma unroll
            for (int q = 0; q < 4; q++) acc[i][j][q] = 0.f;

    for (int k0 = 0; k0 < HDIM; k0 += BK) {
#pragma unroll
        for (int i = 0; i < 8; i++) {           // stage A = attn * V (bf16 in, bf16 out)
            int f = tid + i * 256, row = f >> 4, wc = f & 15;
            uint32_t u = g_v[(size_t)(m0 + row) * 64 + k0 / 2 + wc];
            float2 v = b2f(u);
            int h = (k0 + 2 * wc) >> 5;
            float wgt = saw[row * NHEADS + h];
            sA[row * SAW + wc] = f2b(v.x * wgt, v.y * wgt);
        }
#pragma unroll
        for (int i = 0; i < 4; i++) {           // stage out_w
            int f = tid + i * 256, row = f >> 3, c = f & 7;
            float4 v = *(const float4*)(out_w + (size_t)row * HDIM + k0 + c * 4);
            sB[row * SAW + c * 2]     = f2b(v.x, v.y);
            sB[row * SAW + c * 2 + 1] = f2b(v.z, v.w);
        }
        __syncthreads();
#pragma unroll
        for (int kk = 0; kk < 2; kk++) {
            uint32_t br[8][2];
#pragma unroll
            for (int fn = 0; fn < 8; fn++) {
                int n = wn + fn * 8 + g;
                br[fn][0] = sB[n * SAW + kk * 8 + t];
                br[fn][1] = sB[n * SAW + kk * 8 + t + 4];
            }
#pragma unroll
            for (int fm = 0; fm < 2; fm++) {
                int m = wm + fm * 16 + g;
                uint32_t a0 = sA[m * SAW + kk * 8 + t];
                uint32_t a1 = sA[(m + 8) * SAW + kk * 8 + t];
                uint32_t a2 = sA[m * SAW + kk * 8 + t + 4];
                uint32_t a3 = sA[(m + 8) * SAW + kk * 8 + t + 4];
#pragma unroll
                for (int fn = 0; fn < 8; fn++)
                    MMA(acc[fm][fn], a0, a1, a2, a3, br[fn][0], br[fn][1]);
            }
        }
        __syncthreads();
    }

    float* ob = out + (size_t)batch * CLID * HWSZ;
#pragma unroll
    for (int fm = 0; fm < 2; fm++) {
        int ml = wm + fm * 16 + g;
        int pix0 = spix[ml], pix1 = spix[ml + 8];
#pragma unroll
        for (int fn = 0; fn < 8; fn++) {
            int col = wn + fn * 8 + 2 * t;
            atomicAdd(ob + (size_t)col * HWSZ + pix0,       acc[fm][fn][0]);
            atomicAdd(ob + (size_t)(col + 1) * HWSZ + pix0, acc[fm][fn][1]);
            atomicAdd(ob + (size_t)col * HWSZ + pix1,       acc[fm][fn][2]);
            atomicAdd(ob + (size_t)(col + 1) * HWSZ + pix1, acc[fm][fn][3]);
        }
    }
}

// ============================================================
extern "C" void kernel_launch(void* const* d_in, const int* in_sizes, int n_in,
                              void* d_out, int out_size)
{
    const float* lidar = (const float*)d_in[0];
    const float* tok   = (const float*)d_in[1];
    const int*   ind   = (const int*)  d_in[2];
    const float* gw    = (const float*)d_in[3];
    const float* alpha = (const float*)d_in[4];
    const float* q_w   = (const float*)d_in[5];
    const float* q_b   = (const float*)d_in[6];
    const float* k_w   = (const float*)d_in[7];
    const float* v_w   = (const float*)d_in[8];
    const float* o_w   = (const float*)d_in[9];
    const float* o_b   = (const float*)d_in[10];
    float* out = (float*)d_out;

    k_init<<<(BB * CLID * HWSZ) / 4 / 256, 256>>>((const float4*)lidar, alpha, o_b, (float4*)out);
    dim3 gb(MTOT / BM, 2);
    k_kv<<<gb, 256>>>(tok, k_w, v_w);
    k_qgemm<<<MTOT / BM, 256>>>(lidar, ind, q_w, q_b);
    k_logit_red<<<BB * NHEADS, 256>>>();
    k_out<<<MTOT / BM, 256>>>(ind, gw, alpha, o_w, out);
}

// round 3
// speedup vs baseline: 2.0804x; 1.2372x over previous
#include <cuda_runtime.h>
#include <cuda_bf16.h>
#include <math.h>
#include <stdint.h>

// ---------------- problem constants ----------------
#define BB     4
#define CLID   128
#define HH     256
#define WW     256
#define HWSZ   65536
#define CCAM   256
#define NTOK   8192
#define HDIM   128
#define NHEADS 4
#define MTOT   (BB*NTOK)             // 32768 tokens
#define SCALE  0.17677669529663687f  // 1/sqrt(32)

// ---------------- GEMM tiling ----------------
#define BM 128
#define BN 128
#define BK 32
#define SAW 20    // smem row stride in 32-bit words (BK/2 + 4) -> conflict-free

// ---------------- scratch (device globals) ----------------
__device__ uint32_t g_k[MTOT*64];           // K  [32768][128] bf16 packed
__device__ uint32_t g_v[MTOT*64];           // V  [32768][128] bf16 packed
__device__ float    g_logit[BB*NHEADS*NTOK];
__device__ float2   g_red[BB*NHEADS];       // (max, 1/sumexp)

// ---------------- helpers ----------------
__device__ __forceinline__ uint32_t f2b(float x, float y) {
    __nv_bfloat162 h = __floats2bfloat162_rn(x, y);
    return *reinterpret_cast<uint32_t*>(&h);
}
__device__ __forceinline__ float2 b2f(uint32_t u) {
    __nv_bfloat162 h = *reinterpret_cast<__nv_bfloat162*>(&u);
    return __bfloat1622float2(h);
}

#define MMA(d, a0,a1,a2,a3, b0,b1)                                              \
    asm volatile("mma.sync.aligned.m16n8k16.row.col.f32.bf16.bf16.f32 "         \
                 "{%0,%1,%2,%3},{%4,%5,%6,%7},{%8,%9},{%0,%1,%2,%3};"           \
                 : "+f"(d[0]), "+f"(d[1]), "+f"(d[2]), "+f"(d[3])               \
                 : "r"(a0), "r"(a1), "r"(a2), "r"(a3), "r"(b0), "r"(b1))

// fragment math shared by all GEMM kernels:
//   256 threads = 8 warps, warp grid 4(m) x 2(n); warp tile 32m x 64n
//   m-frags: 2 x m16, n-frags: 8 x n8; k-steps: BK/16 = 2

// ============================================================
// Kernel A: out = lidar + alpha*out_bias[c]   (dense, float4)
// ============================================================
__global__ void k_init(const float4* __restrict__ lidar,
                       const float*  __restrict__ alpha_p,
                       const float*  __restrict__ out_bias,
                       float4* __restrict__ out)
{
    int i = blockIdx.x * blockDim.x + threadIdx.x;
    float alpha = *alpha_p;
    int c = (i >> 14) & 127;
    float bv = alpha * out_bias[c];
    float4 v = lidar[i];
    v.x += bv; v.y += bv; v.z += bv; v.w += bv;
    out[i] = v;
}

// ============================================================
// Kernel B: K = tok @ k_w^T, V = tok @ v_w^T  (M=32768,N=128,K=256) bf16 MMA
// blockIdx.y: 0 -> K, 1 -> V
// ============================================================
__global__ void __launch_bounds__(256)
k_kv(const float* __restrict__ tok,
     const float* __restrict__ k_w,
     const float* __restrict__ v_w)
{
    __shared__ uint32_t sA[BM * SAW];
    __shared__ uint32_t sB[BN * SAW];

    const int m0 = blockIdx.x * BM;
    const float* w = blockIdx.y ? v_w : k_w;
    uint32_t* outp = blockIdx.y ? g_v : g_k;

    const int tid  = threadIdx.x;
    const int lane = tid & 31, wid = tid >> 5;
    const int wm = (wid & 3) * 32, wn = (wid >> 2) * 64;
    const int g = lane >> 2, t = lane & 3;

    float acc[2][8][4];
#pragma unroll
    for (int i = 0; i < 2; i++)
#pragma unroll
        for (int j = 0; j < 8; j++)
#pragma unroll
            for (int q = 0; q < 4; q++) acc[i][j][q] = 0.f;

    for (int k0 = 0; k0 < CCAM; k0 += BK) {
#pragma unroll
        for (int i = 0; i < 4; i++) {           // stage A (tok) -> bf16
            int f = tid + i * 256, row = f >> 3, c = f & 7;
            float4 v = *(const float4*)(tok + (size_t)(m0 + row) * CCAM + k0 + c * 4);
            sA[row * SAW + c * 2]     = f2b(v.x, v.y);
            sA[row * SAW + c * 2 + 1] = f2b(v.z, v.w);
        }
#pragma unroll
        for (int i = 0; i < 4; i++) {           // stage B (weights) -> bf16
            int f = tid + i * 256, row = f >> 3, c = f & 7;
            float4 v = *(const float4*)(w + (size_t)row * CCAM + k0 + c * 4);
            sB[row * SAW + c * 2]     = f2b(v.x, v.y);
            sB[row * SAW + c * 2 + 1] = f2b(v.z, v.w);
        }
        __syncthreads();
#pragma unroll
        for (int kk = 0; kk < 2; kk++) {
            uint32_t br[8][2];
#pragma unroll
            for (int fn = 0; fn < 8; fn++) {
                int n = wn + fn * 8 + g;
                br[fn][0] = sB[n * SAW + kk * 8 + t];
                br[fn][1] = sB[n * SAW + kk * 8 + t + 4];
            }
#pragma unroll
            for (int fm = 0; fm < 2; fm++) {
                int m = wm + fm * 16 + g;
                uint32_t a0 = sA[m * SAW + kk * 8 + t];
                uint32_t a1 = sA[(m + 8) * SAW + kk * 8 + t];
                uint32_t a2 = sA[m * SAW + kk * 8 + t + 4];
                uint32_t a3 = sA[(m + 8) * SAW + kk * 8 + t + 4];
#pragma unroll
                for (int fn = 0; fn < 8; fn++)
                    MMA(acc[fm][fn], a0, a1, a2, a3, br[fn][0], br[fn][1]);
            }
        }
        __syncthreads();
    }

#pragma unroll
    for (int fm = 0; fm < 2; fm++)
#pragma unroll
        for (int fn = 0; fn < 8; fn++) {
            int m = m0 + wm + fm * 16 + g;
            int wcol = wn / 2 + fn * 4 + t;     // word column (2 halves)
            outp[(size_t)m * 64 + wcol]       = f2b(acc[fm][fn][0], acc[fm][fn][1]);
            outp[(size_t)(m + 8) * 64 + wcol] = f2b(acc[fm][fn][2], acc[fm][fn][3]);
        }
}

// ============================================================
// Kernel C: gather lidar at token pixels -> Q = q_w@x + q_bias (bf16 MMA),
// then FUSED logits: logit[b,h,t] = SCALE * <q_h, k_h>  (Q never stored)
// ============================================================
__global__ void __launch_bounds__(256)
k_qgemm(const float* __restrict__ lidar,
        const int*   __restrict__ ind,
        const float* __restrict__ q_w,
        const float* __restrict__ q_bias)
{
    __shared__ uint32_t sA[BM * SAW];
    __shared__ uint32_t sB[BN * SAW];
    __shared__ int spix[BM];

    const int m0    = blockIdx.x * BM;
    const int batch = m0 >> 13;
    const int tid   = threadIdx.x;

    if (tid < BM) {
        int tk = m0 + tid;
        int ii = ind[tk * 2 + 0], jj = ind[tk * 2 + 1];
        ii = min(max(ii, 0), HH - 1);
        jj = min(max(jj, 0), WW - 1);
        spix[tid] = ii * WW + jj;
    }
    __syncthreads();

    const int lane = tid & 31, wid = tid >> 5;
    const int wm = (wid & 3) * 32, wn = (wid >> 2) * 64;
    const int g = lane >> 2, t = lane & 3;

    float acc[2][8][4];
#pragma unroll
    for (int i = 0; i < 2; i++)
#pragma unroll
        for (int j = 0; j < 8; j++)
#pragma unroll
            for (int q = 0; q < 4; q++) acc[i][j][q] = 0.f;

    const float* lb = lidar + (size_t)batch * CLID * HWSZ;

    for (int k0 = 0; k0 < CLID; k0 += BK) {
#pragma unroll
        for (int i = 0; i < 8; i++) {           // gather stage: 128 rows x 16 word-cols
            int f = tid + i * 256, row = f >> 4, p = f & 15;
            const float* lp = lb + (size_t)(k0 + 2 * p) * HWSZ + spix[row];
            sA[row * SAW + p] = f2b(lp[0], lp[HWSZ]);
        }
#pragma unroll
        for (int i = 0; i < 4; i++) {           // stage q_w
            int f = tid + i * 256, row = f >> 3, c = f & 7;
            float4 v = *(const float4*)(q_w + (size_t)row * CLID + k0 + c * 4);
            sB[row * SAW + c * 2]     = f2b(v.x, v.y);
            sB[row * SAW + c * 2 + 1] = f2b(v.z, v.w);
        }
        __syncthreads();
#pragma unroll
        for (int kk = 0; kk < 2; kk++) {
            uint32_t br[8][2];
#pragma unroll
            for (int fn = 0; fn < 8; fn++) {
                int n = wn + fn * 8 + g;
                br[fn][0] = sB[n * SAW + kk * 8 + t];
                br[fn][1] = sB[n * SAW + kk * 8 + t + 4];
            }
#pragma unroll
            for (int fm = 0; fm < 2; fm++) {
                int m = wm + fm * 16 + g;
                uint32_t a0 = sA[m * SAW + kk * 8 + t];
                uint32_t a1 = sA[(m + 8) * SAW + kk * 8 + t];
                uint32_t a2 = sA[m * SAW + kk * 8 + t + 4];
                uint32_t a3 = sA[(m + 8) * SAW + kk * 8 + t + 4];
#pragma unroll
                for (int fn = 0; fn < 8; fn++)
                    MMA(acc[fm][fn], a0, a1, a2, a3, br[fn][0], br[fn][1]);
            }
        }
        __syncthreads();
    }

    // ---- fused logit epilogue ----
    // Each warp's 64 columns (wn..wn+63) = heads (wn>>5) and (wn>>5)+1.
    // Per head: 32 cols spread across 4 t-lanes x 4 fn2 octets x 2 cols.
    // Reduce over t-lanes with shfl.xor(1), shfl.xor(2).
#pragma unroll
    for (int fm = 0; fm < 2; fm++) {
        int m = m0 + wm + fm * 16 + g;
        int tl0 = m & (NTOK - 1), tl1 = (m + 8) & (NTOK - 1);
#pragma unroll
        for (int hoff = 0; hoff < 2; hoff++) {
            float p0 = 0.f, p1 = 0.f;
#pragma unroll
            for (int fn2 = 0; fn2 < 4; fn2++) {
                int fn = hoff * 4 + fn2;
                int n0 = wn + fn * 8 + 2 * t;
                float2 qb = *(const float2*)(q_bias + n0);
                int word = (wn >> 1) + hoff * 16 + fn2 * 4 + t;
                float2 k0v = b2f(g_k[(size_t)m * 64 + word]);
                float2 k1v = b2f(g_k[(size_t)(m + 8) * 64 + word]);
                p0 += (acc[fm][fn][0] + qb.x) * k0v.x + (acc[fm][fn][1] + qb.y) * k0v.y;
                p1 += (acc[fm][fn][2] + qb.x) * k1v.x + (acc[fm][fn][3] + qb.y) * k1v.y;
            }
            p0 += __shfl_xor_sync(0xffffffffu, p0, 1);
            p0 += __shfl_xor_sync(0xffffffffu, p0, 2);
            p1 += __shfl_xor_sync(0xffffffffu, p1, 1);
            p1 += __shfl_xor_sync(0xffffffffu, p1, 2);
            if (t == 0) {
                int h = (wn >> 5) + hoff;
                float* lpo = g_logit + (size_t)(batch * NHEADS + h) * NTOK;
                lpo[tl0] = p0 * SCALE;
                lpo[tl1] = p1 * SCALE;
            }
        }
    }
}

// ============================================================
// Kernel D: per (b,head) max + sumexp over 8192 logits (smem-cached)
// ============================================================
__global__ void __launch_bounds__(256)
k_softred()
{
    __shared__ float sl[NTOK];     // 32 KB
    __shared__ float red[256];
    const int bh = blockIdx.x;
    const float* lp = g_logit + (size_t)bh * NTOK;
    const int tid = threadIdx.x;

    float mx = -1e30f;
    for (int i = tid; i < NTOK; i += 256) {
        float v = lp[i];
        sl[i] = v;
        mx = fmaxf(mx, v);
    }
    red[tid] = mx; __syncthreads();
    for (int s = 128; s > 0; s >>= 1) {
        if (tid < s) red[tid] = fmaxf(red[tid], red[tid + s]);
        __syncthreads();
    }
    mx = red[0]; __syncthreads();

    float sum = 0.f;
    for (int i = tid; i < NTOK; i += 256) sum += expf(sl[i] - mx);
    red[tid] = sum; __syncthreads();
    for (int s = 128; s > 0; s >>= 1) {
        if (tid < s) red[tid] += red[tid + s];
        __syncthreads();
    }
    if (tid == 0) g_red[bh] = make_float2(mx, 1.0f / red[0]);
}

// ============================================================
// Kernel E: fused = attn*V; y = out_w @ fused (bf16 MMA); scatter-add
// ============================================================
__global__ void __launch_bounds__(256)
k_out(const int*   __restrict__ ind,
      const float* __restrict__ gw,
      const float* __restrict__ alpha_p,
      const float* __restrict__ out_w,
      float* __restrict__ out)
{
    __shared__ uint32_t sA[BM * SAW];
    __shared__ uint32_t sB[BN * SAW];
    __shared__ int   spix[BM];
    __shared__ float saw[BM * NHEADS];

    const int m0    = blockIdx.x * BM;
    const int batch = m0 >> 13;
    const int tid   = threadIdx.x;

    if (tid < BM) {
        int tk = m0 + tid;
        int ii = ind[tk * 2 + 0], jj = ind[tk * 2 + 1];
        ii = min(max(ii, 0), HH - 1);
        jj = min(max(jj, 0), WW - 1);
        spix[tid] = ii * WW + jj;
    }
    {
        float alpha = *alpha_p;
#pragma unroll
        for (int j = 0; j < 2; j++) {
            int idx = tid + j * 256;            // 512 = 128 tokens x 4 heads
            int tl = idx & 127, h = idx >> 7;
            int tloc = (m0 & (NTOK - 1)) + tl;
            float  lt = g_logit[(size_t)(batch * NHEADS + h) * NTOK + tloc];
            float2 r  = g_red[batch * NHEADS + h];
            saw[tl * NHEADS + h] = expf(lt - r.x) * r.y * gw[(size_t)batch * NTOK + tloc] * alpha;
        }
    }
    __syncthreads();

    const int lane = tid & 31, wid = tid >> 5;
    const int wm = (wid & 3) * 32, wn = (wid >> 2) * 64;
    const int g = lane >> 2, t = lane & 3;

    float acc[2][8][4];
#pragma unroll
    for (int i = 0; i < 2; i++)
#pragma unroll
        for (int j = 0; j < 8; j++)
#pragma unroll
            for (int q = 0; q < 4; q++) acc[i][j][q] = 0.f;

    for (int k0 = 0; k0 < HDIM; k0 += BK) {
#pragma unroll
        for (int i = 0; i < 8; i++) {           // stage A = attn * V (bf16 in/out)
            int f = tid + i * 256, row = f >> 4, wc = f & 15;
            uint32_t u = g_v[(size_t)(m0 + row) * 64 + k0 / 2 + wc];
            float2 v = b2f(u);
            int h = (k0 + 2 * wc) >> 5;
            float wgt = saw[row * NHEADS + h];
            sA[row * SAW + wc] = f2b(v.x * wgt, v.y * wgt);
        }
#pragma unroll
        for (int i = 0; i < 4; i++) {           // stage out_w
            int f = tid + i * 256, row = f >> 3, c = f & 7;
            float4 v = *(const float4*)(out_w + (size_t)row * HDIM + k0 + c * 4);
            sB[row * SAW + c * 2]     = f2b(v.x, v.y);
            sB[row * SAW + c * 2 + 1] = f2b(v.z, v.w);
        }
        __syncthreads();
#pragma unroll
        for (int kk = 0; kk < 2; kk++) {
            uint32_t br[8][2];
#pragma unroll
            for (int fn = 0; fn < 8; fn++) {
                int n = wn + fn * 8 + g;
                br[fn][0] = sB[n * SAW + kk * 8 + t];
                br[fn][1] = sB[n * SAW + kk * 8 + t + 4];
            }
#pragma unroll
            for (int fm = 0; fm < 2; fm++) {
                int m = wm + fm * 16 + g;
                uint32_t a0 = sA[m * SAW + kk * 8 + t];
                uint32_t a1 = sA[(m + 8) * SAW + kk * 8 + t];
                uint32_t a2 = sA[m * SAW + kk * 8 + t + 4];
                uint32_t a3 = sA[(m + 8) * SAW + kk * 8 + t + 4];
#pragma unroll
                for (int fn = 0; fn < 8; fn++)
                    MMA(acc[fm][fn], a0, a1, a2, a3, br[fn][0], br[fn][1]);
            }
        }
        __syncthreads();
    }

    float* ob = out + (size_t)batch * CLID * HWSZ;
#pragma unroll
    for (int fm = 0; fm < 2; fm++) {
        int ml = wm + fm * 16 + g;
        int pix0 = spix[ml], pix1 = spix[ml + 8];
#pragma unroll
        for (int fn = 0; fn < 8; fn++) {
            int col = wn + fn * 8 + 2 * t;
            atomicAdd(ob + (size_t)col * HWSZ + pix0,       acc[fm][fn][0]);
            atomicAdd(ob + (size_t)(col + 1) * HWSZ + pix0, acc[fm][fn][1]);
            atomicAdd(ob + (size_t)col * HWSZ + pix1,       acc[fm][fn][2]);
            atomicAdd(ob + (size_t)(col + 1) * HWSZ + pix1, acc[fm][fn][3]);
        }
    }
}

// ============================================================
extern "C" void kernel_launch(void* const* d_in, const int* in_sizes, int n_in,
                              void* d_out, int out_size)
{
    const float* lidar = (const float*)d_in[0];
    const float* tok   = (const float*)d_in[1];
    const int*   ind   = (const int*)  d_in[2];
    const float* gw    = (const float*)d_in[3];
    const float* alpha = (const float*)d_in[4];
    const float* q_w   = (const float*)d_in[5];
    const float* q_b   = (const float*)d_in[6];
    const float* k_w   = (const float*)d_in[7];
    const float* v_w   = (const float*)d_in[8];
    const float* o_w   = (const float*)d_in[9];
    const float* o_b   = (const float*)d_in[10];
    float* out = (float*)d_out;

    k_init<<<(BB * CLID * HWSZ) / 4 / 256, 256>>>((const float4*)lidar, alpha, o_b, (float4*)out);
    dim3 gb(MTOT / BM, 2);
    k_kv<<<gb, 256>>>(tok, k_w, v_w);
    k_qgemm<<<MTOT / BM, 256>>>(lidar, ind, q_w, q_b);
    k_softred<<<BB * NHEADS, 256>>>();
    k_out<<<MTOT / BM, 256>>>(ind, gw, alpha, o_w, out);
}